// round 11
// baseline (speedup 1.0000x reference)
#include <cuda_runtime.h>
#include <cuda_fp16.h>

#define NN 100000
#define NP (NN + 128)    // padded rows so node-kernel cp.async never reads OOB
#define EE 600000
#define HD 128
#define OD3 64
#define KSB 144          // SMEM row stride bytes for 64 fp16 cols (+8 elem pad)
#define BSE 72           // same in elements

typedef unsigned long long u64;
typedef unsigned int u32;

// ---------------- scratch (device globals) ----------------
__device__ __align__(16) __half g_xh[(size_t)NP * HD];    // fp16 copy of x
__device__ __align__(16) __half g_agg[(size_t)NP * HD];   // fp16 mean-agg
__device__ __align__(16) __half g_h[(size_t)NP * HD];     // fp16 hidden acts
__device__ int   g_cnt[NN];          // zero at rest; re-zeroed by k_scan
__device__ int   g_rowstart[NN + 1];
__device__ int   g_cursor[NN];
__device__ int   g_csrc[EE];
// fp16 weight images: [layer][chunk 0..3][n*BSE + kk]; B = W^T.
// chunks 0,1 = Wl k[0:64),[64:128); chunks 2,3 = Wr.
__device__ __align__(16) __half g_bimg[3][4][HD * BSE];

// ---------------- PTX helpers ----------------
__device__ __forceinline__ u32 smem_u32(const void* p) {
    u32 a;
    asm("{ .reg .u64 t; cvta.to.shared.u64 t, %1; cvt.u32.u64 %0, t; }" : "=r"(a) : "l"(p));
    return a;
}
__device__ __forceinline__ void ldsm4(u32* r, u32 addr) {
    asm volatile("ldmatrix.sync.aligned.m8n8.x4.shared.b16 {%0,%1,%2,%3}, [%4];"
                 : "=r"(r[0]), "=r"(r[1]), "=r"(r[2]), "=r"(r[3]) : "r"(addr));
}
__device__ __forceinline__ void mma16816(float* c, const u32* a, u32 b0, u32 b1) {
    asm volatile("mma.sync.aligned.m16n8k16.row.col.f32.f16.f16.f32 "
                 "{%0,%1,%2,%3}, {%4,%5,%6,%7}, {%8,%9}, {%0,%1,%2,%3};"
                 : "+f"(c[0]), "+f"(c[1]), "+f"(c[2]), "+f"(c[3])
                 : "r"(a[0]), "r"(a[1]), "r"(a[2]), "r"(a[3]), "r"(b0), "r"(b1));
}
__device__ __forceinline__ void cpasync16(u32 smem_addr, const void* gptr) {
    asm volatile("cp.async.cg.shared.global [%0], [%1], 16;"
                 :: "r"(smem_addr), "l"(gptr) : "memory");
}
#define CP_COMMIT() asm volatile("cp.async.commit_group;" ::: "memory")

// ================= CSR build =================
__global__ void k_hist(const int* __restrict__ dst) {
    int e = blockIdx.x * blockDim.x + threadIdx.x;
    if (e < EE) atomicAdd(&g_cnt[dst[e]], 1);
}

__global__ void k_scan() {   // single block, 1024 threads; restores g_cnt=0
    __shared__ int sh[1024];
    const int tid = threadIdx.x;
    const int CH = (NN + 1023) / 1024;
    int base = tid * CH;
    int end  = min(base + CH, NN);
    int s = 0;
    for (int i = base; i < end; i++) s += g_cnt[i];
    sh[tid] = s;
    __syncthreads();
    for (int off = 1; off < 1024; off <<= 1) {
        int v = (tid >= off) ? sh[tid - off] : 0;
        __syncthreads();
        sh[tid] += v;
        __syncthreads();
    }
    int run = sh[tid] - s;
    for (int i = base; i < end; i++) {
        int c = g_cnt[i];
        g_rowstart[i] = run;
        g_cursor[i]   = run;
        g_cnt[i]      = 0;
        run += c;
    }
    if (tid == 0) g_rowstart[NN] = EE;
}

__global__ void k_slot(const int* __restrict__ src, const int* __restrict__ dst) {
    int e = blockIdx.x * blockDim.x + threadIdx.x;
    if (e < EE) {
        int d = dst[e];
        int slot = atomicAdd(&g_cursor[d], 1);
        g_csrc[slot] = src[e];
    }
}

// ================= x -> fp16 copy =================
__global__ void k_xhalf(const float* __restrict__ x) {
    int t = blockIdx.x * blockDim.x + threadIdx.x;
    if (t >= NN * HD / 8) return;
    float4 v0 = __ldg((const float4*)x + t * 2);
    float4 v1 = __ldg((const float4*)x + t * 2 + 1);
    __half2 h0 = __floats2half2_rn(v0.x, v0.y);
    __half2 h1 = __floats2half2_rn(v0.z, v0.w);
    __half2 h2 = __floats2half2_rn(v1.x, v1.y);
    __half2 h3 = __floats2half2_rn(v1.z, v1.w);
    uint4 p;
    p.x = *(u32*)&h0; p.y = *(u32*)&h1; p.z = *(u32*)&h2; p.w = *(u32*)&h3;
    ((uint4*)g_xh)[t] = p;
}

// ================= mean aggregation: warp per node, fp16 rows =================
__global__ void k_gather(const __half* __restrict__ xin) {
    int w = (blockIdx.x * blockDim.x + threadIdx.x) >> 5;
    if (w >= NN) return;
    int lane = threadIdx.x & 31;
    int b = g_rowstart[w], e2 = g_rowstart[w + 1];
    float a0 = 0.f, a1 = 0.f, a2 = 0.f, a3 = 0.f;
    float b0 = 0.f, b1 = 0.f, b2 = 0.f, b3 = 0.f;
    int j = b;
    for (; j + 1 < e2; j += 2) {
        int s0 = __ldg(&g_csrc[j]);
        int s1 = __ldg(&g_csrc[j + 1]);
        uint2 p0 = __ldg((const uint2*)(xin + (size_t)s0 * HD) + lane);
        uint2 p1 = __ldg((const uint2*)(xin + (size_t)s1 * HD) + lane);
        float2 f0 = __half22float2(*(__half2*)&p0.x);
        float2 f1 = __half22float2(*(__half2*)&p0.y);
        float2 g0 = __half22float2(*(__half2*)&p1.x);
        float2 g1 = __half22float2(*(__half2*)&p1.y);
        a0 += f0.x; a1 += f0.y; a2 += f1.x; a3 += f1.y;
        b0 += g0.x; b1 += g0.y; b2 += g1.x; b3 += g1.y;
    }
    if (j < e2) {
        int s0 = __ldg(&g_csrc[j]);
        uint2 p0 = __ldg((const uint2*)(xin + (size_t)s0 * HD) + lane);
        float2 f0 = __half22float2(*(__half2*)&p0.x);
        float2 f1 = __half22float2(*(__half2*)&p0.y);
        a0 += f0.x; a1 += f0.y; a2 += f1.x; a3 += f1.y;
    }
    float inv = 1.0f / fmaxf((float)(e2 - b), 1.0f);
    __half2 o0 = __floats2half2_rn((a0 + b0) * inv, (a1 + b1) * inv);
    __half2 o1 = __floats2half2_rn((a2 + b2) * inv, (a3 + b3) * inv);
    uint2 o;
    o.x = *(u32*)&o0; o.y = *(u32*)&o1;
    ((uint2*)(g_agg + (size_t)w * HD))[lane] = o;
}

// ================= weight prepack (all 3 layers, one launch) =================
__global__ void k_bpackall(const float* __restrict__ Wl1, const float* __restrict__ Wr1,
                           const float* __restrict__ Wl2, const float* __restrict__ Wr2,
                           const float* __restrict__ Wl3, const float* __restrict__ Wr3) {
    int t = blockIdx.x * blockDim.x + threadIdx.x;
    if (t >= 3 * 4 * 64 * HD) return;
    int layer = t / (4 * 64 * HD);
    int rem   = t % (4 * 64 * HD);
    int chunk = rem / (64 * HD);
    int rem2  = rem % (64 * HD);
    int kk = rem2 / HD, n = rem2 % HD;
    int N_ = (layer == 2) ? OD3 : HD;
    if (n >= N_) return;
    const float* W;
    if (layer == 0)      W = (chunk < 2) ? Wl1 : Wr1;
    else if (layer == 1) W = (chunk < 2) ? Wl2 : Wr2;
    else                 W = (chunk < 2) ? Wl3 : Wr3;
    int gk = (chunk & 1) * 64 + kk;
    g_bimg[layer][chunk][n * BSE + kk] = __float2half_rn(__ldg(W + gk * N_ + n));
}

// ================= pipelined node GEMM: 512 threads, 4x4 warp grid =============
// Block: 128 nodes, 16 warps; warp tile 32 rows x N_/4 cols (acc = 32 regs max).
// K = 256 as 4 chunks of 64 (agg,agg,x,x); A and B double-buffered cp.async.
// B fragments via ldsm4 (two n8 tiles per instruction).
template<int N_, bool LAST>
__global__ __launch_bounds__(512, 2)
void k_node(const __half* __restrict__ xh, void* __restrict__ hout, int layer,
            const float* __restrict__ bl, const float* __restrict__ g,
            const float* __restrict__ be, const float* __restrict__ rm,
            const float* __restrict__ rv)
{
    extern __shared__ char smem[];
    constexpr int ABYT = 128 * KSB;
    constexpr int BBYT = N_ * KSB;
    constexpr int SM_B0 = 2 * ABYT;
    constexpr int SM_SC = 2 * ABYT + 2 * BBYT;
    constexpr int SM_SH = SM_SC + 512;
    constexpr int NJ  = N_ / 32;     // n8 tiles per warp (4 for N=128, 2 for N=64)
    constexpr int NJ2 = NJ / 2;      // ldsm4 B loads per k16

    const int tid  = threadIdx.x;
    const int wid  = tid >> 5;
    const int lane = tid & 31;
    const int wr   = (wid >> 2) * 32;        // row group: 0,32,64,96
    const int wc   = (wid & 3) * (N_ / 4);   // col group
    const int nb   = blockIdx.x * 128;
    const u32 sb   = smem_u32(smem);

    // BN scale/shift (bias folded)
    if (tid < N_) {
        float s, sh;
        if (!LAST) {
            float sc_ = __ldg(&g[tid]) * rsqrtf(__ldg(&rv[tid]) + 1e-5f);
            s  = sc_;
            sh = (__ldg(&bl[tid]) - __ldg(&rm[tid])) * sc_ + __ldg(&be[tid]);
        } else {
            s  = 1.0f;
            sh = __ldg(&bl[tid]);
        }
        *(float*)(smem + SM_SC + tid * 4) = s;
        *(float*)(smem + SM_SH + tid * 4) = sh;
    }

    // ---- async stage of one chunk ----
    auto stage = [&](int cc, int buf) {
        const __half* asrc = (cc < 2) ? g_agg : xh;
        const int co = (cc & 1) * 128;       // byte offset within 256B row
        const u32 adst = sb + buf * ABYT;
        for (int idx = tid; idx < 1024; idx += 512) {
            int r = idx >> 3, i = idx & 7;
            cpasync16(adst + r * KSB + i * 16,
                      (const char*)(asrc + (size_t)(nb + r) * HD) + co + i * 16);
        }
        const char* bsrc = (const char*)&g_bimg[layer][cc][0];
        const u32 bdst = sb + SM_B0 + buf * BBYT;
        for (int i = tid; i < BBYT / 16; i += 512)
            cpasync16(bdst + i * 16, bsrc + i * 16);
    };

    stage(0, 0);
    CP_COMMIT();

    // ldmatrix lane offsets (x4 pattern: row = lane&15, 16B chunk = lane>>4)
    const u32 aOff = (u32)((wr + (lane & 15)) * KSB + (lane >> 4) * 16);
    const u32 bOff = (u32)((wc + (lane & 15)) * KSB + (lane >> 4) * 16);

    float acc[2][NJ][4];
    #pragma unroll
    for (int m = 0; m < 2; m++)
        #pragma unroll
        for (int j = 0; j < NJ; j++) {
            acc[m][j][0] = 0.f; acc[m][j][1] = 0.f;
            acc[m][j][2] = 0.f; acc[m][j][3] = 0.f;
        }

    #pragma unroll
    for (int chunk = 0; chunk < 4; chunk++) {
        if (chunk < 3) {
            stage(chunk + 1, (chunk + 1) & 1);
            CP_COMMIT();
            asm volatile("cp.async.wait_group 1;" ::: "memory");
        } else {
            asm volatile("cp.async.wait_group 0;" ::: "memory");
        }
        __syncthreads();

        const u32 abuf = sb + (chunk & 1) * ABYT + aOff;
        const u32 bbuf = sb + SM_B0 + (chunk & 1) * BBYT + bOff;
        #pragma unroll
        for (int k16 = 0; k16 < 4; k16++) {
            u32 a0[4], a1[4];
            ldsm4(a0, abuf + k16 * 32);
            ldsm4(a1, abuf + 16 * KSB + k16 * 32);
            #pragma unroll
            for (int jp = 0; jp < NJ2; jp++) {
                u32 bb[4];
                ldsm4(bb, bbuf + jp * 16 * KSB + k16 * 32);
                // bb: [0]=n8 tile 2jp k0-7, [1]=tile 2jp+1 k0-7, [2]=tile 2jp k8-15, [3]=tile 2jp+1 k8-15
                mma16816(acc[0][2 * jp],     a0, bb[0], bb[2]);
                mma16816(acc[1][2 * jp],     a1, bb[0], bb[2]);
                mma16816(acc[0][2 * jp + 1], a0, bb[1], bb[3]);
                mma16816(acc[1][2 * jp + 1], a1, bb[1], bb[3]);
            }
        }
        __syncthreads();
    }

    // ---- epilogue ----
    const int cb = (lane & 3) * 2;
    #pragma unroll
    for (int m = 0; m < 2; m++) {
        int n0 = nb + wr + m * 16 + (lane >> 2);
        #pragma unroll
        for (int j = 0; j < NJ; j++) {
            int c = wc + j * 8 + cb;
            float s0 = *(const float*)(smem + SM_SC + c * 4);
            float s1 = *(const float*)(smem + SM_SC + (c + 1) * 4);
            float h0 = *(const float*)(smem + SM_SH + c * 4);
            float h1 = *(const float*)(smem + SM_SH + (c + 1) * 4);
            #pragma unroll
            for (int hh = 0; hh < 2; hh++) {
                int n = n0 + hh * 8;
                if (n >= NN) continue;
                float vx = acc[m][j][hh * 2 + 0] * s0 + h0;
                float vy = acc[m][j][hh * 2 + 1] * s1 + h1;
                if (!LAST) {
                    vx = fmaxf(vx, 0.f);
                    vy = fmaxf(vy, 0.f);
                    __half2 hv = __floats2half2_rn(vx, vy);
                    *(u32*)((__half*)hout + (size_t)n * N_ + c) = *(u32*)&hv;
                } else {
                    float2 o; o.x = vx; o.y = vy;
                    *(float2*)((float*)hout + (size_t)n * N_ + c) = o;
                }
            }
        }
    }
}

// ================= launch =================
extern "C" void kernel_launch(void* const* d_in, const int* in_sizes, int n_in,
                              void* d_out, int out_size) {
    const float* x    = (const float*)d_in[0];
    const int*   ei   = (const int*)  d_in[1];
    const float* Wl1  = (const float*)d_in[2];
    const float* bl1  = (const float*)d_in[3];
    const float* Wr1  = (const float*)d_in[4];
    const float* g1   = (const float*)d_in[5];
    const float* be1  = (const float*)d_in[6];
    const float* rm1  = (const float*)d_in[7];
    const float* rv1  = (const float*)d_in[8];
    const float* Wl2  = (const float*)d_in[9];
    const float* bl2  = (const float*)d_in[10];
    const float* Wr2  = (const float*)d_in[11];
    const float* g2   = (const float*)d_in[12];
    const float* be2  = (const float*)d_in[13];
    const float* rm2  = (const float*)d_in[14];
    const float* rv2  = (const float*)d_in[15];
    const float* Wl3  = (const float*)d_in[16];
    const float* bl3  = (const float*)d_in[17];
    const float* Wr3  = (const float*)d_in[18];
    const int* src = ei;
    const int* dst = ei + EE;
    float* out = (float*)d_out;

    __half *xh_p, *h_p;
    cudaGetSymbolAddress((void**)&xh_p, g_xh);
    cudaGetSymbolAddress((void**)&h_p,  g_h);

    constexpr int SMEM12 = 2 * 128 * KSB + 2 * HD  * KSB + 1024;   // 74752
    constexpr int SMEM3  = 2 * 128 * KSB + 2 * OD3 * KSB + 1024;   // 56320
    cudaFuncSetAttribute(k_node<HD, false>, cudaFuncAttributeMaxDynamicSharedMemorySize, SMEM12);
    cudaFuncSetAttribute(k_node<OD3, true>, cudaFuncAttributeMaxDynamicSharedMemorySize, SMEM3);

    const int EB = (EE + 255) / 256;
    const int GB = (NN * 32 + 255) / 256;
    const int NB = (NN + 127) / 128;   // 782

    // CSR build + fp16 conversions + weight pack
    k_hist<<<EB, 256>>>(dst);
    k_scan<<<1, 1024>>>();
    k_slot<<<EB, 256>>>(src, dst);
    k_xhalf<<<(NN * HD / 8 + 255) / 256, 256>>>(x);
    k_bpackall<<<(3 * 4 * 64 * HD + 255) / 256, 256>>>(Wl1, Wr1, Wl2, Wr2, Wl3, Wr3);

    // layer 1
    k_gather<<<GB, 256>>>(xh_p);
    k_node<HD, false><<<NB, 512, SMEM12>>>(xh_p, h_p, 0, bl1, g1, be1, rm1, rv1);

    // layer 2 (in place safe: node reads only its own rows of g_h / g_agg)
    k_gather<<<GB, 256>>>(h_p);
    k_node<HD, false><<<NB, 512, SMEM12>>>(h_p, h_p, 1, bl2, g2, be2, rm2, rv2);

    // layer 3
    k_gather<<<GB, 256>>>(h_p);
    k_node<OD3, true><<<NB, 512, SMEM3>>>(h_p, out, 2, bl3, bl3, bl3, bl3, bl3);
}

// round 13
// speedup vs baseline: 1.0055x; 1.0055x over previous
#include <cuda_runtime.h>
#include <cuda_fp16.h>

#define NN 100000
#define NP (NN + 128)    // padded rows so node-kernel cp.async never reads OOB
#define EE 600000
#define HD 128
#define OD3 64
#define KSB 144          // SMEM row stride bytes for 64 fp16 cols (+8 elem pad)
#define BSE 72           // same in elements
#define NTILE 782        // ceil(NN/128)
#define GRID 304         // ~2 blocks/SM, grid-stride over tiles

typedef unsigned long long u64;
typedef unsigned int u32;

// ---------------- scratch (device globals) ----------------
__device__ __align__(16) __half g_xh[(size_t)NP * HD];    // fp16 copy of x
__device__ __align__(16) __half g_agg[(size_t)NP * HD];   // fp16 mean-agg
__device__ __align__(16) __half g_h[(size_t)NP * HD];     // fp16 hidden acts
__device__ int   g_cnt[NN];          // zero at rest; re-zeroed by k_scan
__device__ int   g_rowstart[NN + 1];
__device__ int   g_cursor[NN];
__device__ int   g_csrc[EE];
// fp16 weight images, DENSELY PACKED PER LAYER so each layer's 4 chunk images
// are contiguous: layer1 @0 (4*HD*BSE), layer2 @4*HD*BSE, layer3 @8*HD*BSE
// (4*OD3*BSE). Within a layer: chunk*N_*BSE + n*BSE + kk. B = W^T.
#define BIMG_L2 (4 * HD * BSE)
#define BIMG_L3 (8 * HD * BSE)
__device__ __align__(16) __half g_bimg[8 * HD * BSE + 4 * OD3 * BSE];

// ---------------- PTX helpers ----------------
__device__ __forceinline__ u32 smem_u32(const void* p) {
    u32 a;
    asm("{ .reg .u64 t; cvta.to.shared.u64 t, %1; cvt.u32.u64 %0, t; }" : "=r"(a) : "l"(p));
    return a;
}
__device__ __forceinline__ void ldsm4(u32* r, u32 addr) {
    asm volatile("ldmatrix.sync.aligned.m8n8.x4.shared.b16 {%0,%1,%2,%3}, [%4];"
                 : "=r"(r[0]), "=r"(r[1]), "=r"(r[2]), "=r"(r[3]) : "r"(addr));
}
__device__ __forceinline__ void mma16816(float* c, const u32* a, u32 b0, u32 b1) {
    asm volatile("mma.sync.aligned.m16n8k16.row.col.f32.f16.f16.f32 "
                 "{%0,%1,%2,%3}, {%4,%5,%6,%7}, {%8,%9}, {%0,%1,%2,%3};"
                 : "+f"(c[0]), "+f"(c[1]), "+f"(c[2]), "+f"(c[3])
                 : "r"(a[0]), "r"(a[1]), "r"(a[2]), "r"(a[3]), "r"(b0), "r"(b1));
}
__device__ __forceinline__ void cpasync16(u32 smem_addr, const void* gptr) {
    asm volatile("cp.async.cg.shared.global [%0], [%1], 16;"
                 :: "r"(smem_addr), "l"(gptr) : "memory");
}
#define CP_COMMIT() asm volatile("cp.async.commit_group;" ::: "memory")

// ================= CSR build =================
__global__ void k_hist(const int* __restrict__ dst) {
    int e = blockIdx.x * blockDim.x + threadIdx.x;
    if (e < EE) atomicAdd(&g_cnt[dst[e]], 1);
}

__global__ void k_scan() {   // single block, 1024 threads; restores g_cnt=0
    __shared__ int sh[1024];
    const int tid = threadIdx.x;
    const int CH = (NN + 1023) / 1024;
    int base = tid * CH;
    int end  = min(base + CH, NN);
    int s = 0;
    for (int i = base; i < end; i++) s += g_cnt[i];
    sh[tid] = s;
    __syncthreads();
    for (int off = 1; off < 1024; off <<= 1) {
        int v = (tid >= off) ? sh[tid - off] : 0;
        __syncthreads();
        sh[tid] += v;
        __syncthreads();
    }
    int run = sh[tid] - s;
    for (int i = base; i < end; i++) {
        int c = g_cnt[i];
        g_rowstart[i] = run;
        g_cursor[i]   = run;
        g_cnt[i]      = 0;
        run += c;
    }
    if (tid == 0) g_rowstart[NN] = EE;
}

__global__ void k_slot(const int* __restrict__ src, const int* __restrict__ dst) {
    int e = blockIdx.x * blockDim.x + threadIdx.x;
    if (e < EE) {
        int d = dst[e];
        int slot = atomicAdd(&g_cursor[d], 1);
        g_csrc[slot] = src[e];
    }
}

// ================= x -> fp16 copy =================
__global__ void k_xhalf(const float* __restrict__ x) {
    int t = blockIdx.x * blockDim.x + threadIdx.x;
    if (t >= NN * HD / 8) return;
    float4 v0 = __ldg((const float4*)x + t * 2);
    float4 v1 = __ldg((const float4*)x + t * 2 + 1);
    __half2 h0 = __floats2half2_rn(v0.x, v0.y);
    __half2 h1 = __floats2half2_rn(v0.z, v0.w);
    __half2 h2 = __floats2half2_rn(v1.x, v1.y);
    __half2 h3 = __floats2half2_rn(v1.z, v1.w);
    uint4 p;
    p.x = *(u32*)&h0; p.y = *(u32*)&h1; p.z = *(u32*)&h2; p.w = *(u32*)&h3;
    ((uint4*)g_xh)[t] = p;
}

// ================= mean aggregation: warp per node, fp16 rows =================
__global__ void k_gather(const __half* __restrict__ xin) {
    int w = (blockIdx.x * blockDim.x + threadIdx.x) >> 5;
    if (w >= NN) return;
    int lane = threadIdx.x & 31;
    int b = g_rowstart[w], e2 = g_rowstart[w + 1];
    float a0 = 0.f, a1 = 0.f, a2 = 0.f, a3 = 0.f;
    float b0 = 0.f, b1 = 0.f, b2 = 0.f, b3 = 0.f;
    int j = b;
    for (; j + 1 < e2; j += 2) {
        int s0 = __ldg(&g_csrc[j]);
        int s1 = __ldg(&g_csrc[j + 1]);
        uint2 p0 = __ldg((const uint2*)(xin + (size_t)s0 * HD) + lane);
        uint2 p1 = __ldg((const uint2*)(xin + (size_t)s1 * HD) + lane);
        float2 f0 = __half22float2(*(__half2*)&p0.x);
        float2 f1 = __half22float2(*(__half2*)&p0.y);
        float2 g0 = __half22float2(*(__half2*)&p1.x);
        float2 g1 = __half22float2(*(__half2*)&p1.y);
        a0 += f0.x; a1 += f0.y; a2 += f1.x; a3 += f1.y;
        b0 += g0.x; b1 += g0.y; b2 += g1.x; b3 += g1.y;
    }
    if (j < e2) {
        int s0 = __ldg(&g_csrc[j]);
        uint2 p0 = __ldg((const uint2*)(xin + (size_t)s0 * HD) + lane);
        float2 f0 = __half22float2(*(__half2*)&p0.x);
        float2 f1 = __half22float2(*(__half2*)&p0.y);
        a0 += f0.x; a1 += f0.y; a2 += f1.x; a3 += f1.y;
    }
    float inv = 1.0f / fmaxf((float)(e2 - b), 1.0f);
    __half2 o0 = __floats2half2_rn((a0 + b0) * inv, (a1 + b1) * inv);
    __half2 o1 = __floats2half2_rn((a2 + b2) * inv, (a3 + b3) * inv);
    uint2 o;
    o.x = *(u32*)&o0; o.y = *(u32*)&o1;
    ((uint2*)(g_agg + (size_t)w * HD))[lane] = o;
}

// ================= weight prepack (all 3 layers, one launch) =================
// Densely packed per layer: base + chunk*N_*BSE + n*BSE + kk.
__global__ void k_bpackall(const float* __restrict__ Wl1, const float* __restrict__ Wr1,
                           const float* __restrict__ Wl2, const float* __restrict__ Wr2,
                           const float* __restrict__ Wl3, const float* __restrict__ Wr3) {
    int t = blockIdx.x * blockDim.x + threadIdx.x;
    if (t >= 3 * 4 * 64 * HD) return;
    int layer = t / (4 * 64 * HD);
    int rem   = t % (4 * 64 * HD);
    int chunk = rem / (64 * HD);
    int rem2  = rem % (64 * HD);
    int kk = rem2 / HD, n = rem2 % HD;
    int N_ = (layer == 2) ? OD3 : HD;
    if (n >= N_) return;
    const float* W;
    int base;
    if (layer == 0)      { W = (chunk < 2) ? Wl1 : Wr1; base = 0; }
    else if (layer == 1) { W = (chunk < 2) ? Wl2 : Wr2; base = BIMG_L2; }
    else                 { W = (chunk < 2) ? Wl3 : Wr3; base = BIMG_L3; }
    int gk = (chunk & 1) * 64 + kk;
    g_bimg[base + chunk * N_ * BSE + n * BSE + kk] = __float2half_rn(__ldg(W + gk * N_ + n));
}

// ================= grid-stride node GEMM, B fully SMEM-resident ===============
// GRID blocks, 512 threads = 16 warps (4 row x 4 col groups), warp tile 32 x N_/4.
// Each block loops tiles (128 nodes) via grid stride. B (all 4 chunks, densely
// packed) staged ONCE per block; A chunks flow through a flat double-buffered
// cp.async pipeline across tile boundaries (global chunk index q).
template<int N_, bool LAST>
__global__ __launch_bounds__(512, 2)
void k_node(const __half* __restrict__ xh, void* __restrict__ hout,
            const __half* __restrict__ bimg,
            const float* __restrict__ bl, const float* __restrict__ g,
            const float* __restrict__ be, const float* __restrict__ rm,
            const float* __restrict__ rv)
{
    extern __shared__ char smem[];
    constexpr int ABYT = 128 * KSB;          // one A chunk buffer (18432)
    constexpr int BBYT = N_ * KSB;           // one B chunk image
    constexpr int SM_B  = 2 * ABYT;
    constexpr int SM_SC = 2 * ABYT + 4 * BBYT;
    constexpr int SM_SH = SM_SC + 512;
    constexpr int NJ  = N_ / 32;             // n8 tiles per warp
    constexpr int NJ2 = NJ / 2;

    const int tid  = threadIdx.x;
    const int wid  = tid >> 5;
    const int lane = tid & 31;
    const int wr   = (wid >> 2) * 32;
    const int wc   = (wid & 3) * (N_ / 4);
    const int bid  = blockIdx.x;
    const u32 sb   = smem_u32(smem);

    // BN scale/shift (bias folded) — layer constants, computed once
    if (tid < N_) {
        float s, sh;
        if (!LAST) {
            float sc_ = __ldg(&g[tid]) * rsqrtf(__ldg(&rv[tid]) + 1e-5f);
            s  = sc_;
            sh = (__ldg(&bl[tid]) - __ldg(&rm[tid])) * sc_ + __ldg(&be[tid]);
        } else {
            s  = 1.0f;
            sh = __ldg(&bl[tid]);
        }
        *(float*)(smem + SM_SC + tid * 4) = s;
        *(float*)(smem + SM_SH + tid * 4) = sh;
    }

    // ---- stage ALL 4 B chunk images once (densely packed: raw byte copy) ----
    {
        const char* bsrc = (const char*)bimg;
        for (int i = tid; i < 4 * BBYT / 16; i += 512)
            cpasync16(sb + SM_B + i * 16, bsrc + i * 16);
    }

    const int ntiles = (NTILE - 1 - bid) / GRID + 1;
    const int Q = ntiles * 4;

    // ---- A chunk stage by flat index q ----
    auto stageq = [&](int qq) {
        int cc = qq & 3;
        size_t nb2 = (size_t)(bid + (qq >> 2) * GRID) * 128;
        const __half* asrc = (cc < 2) ? g_agg : xh;
        const int co = (cc & 1) * 128;       // byte offset within 256B row
        const u32 adst = sb + (qq & 1) * ABYT;
        for (int idx = tid; idx < 1024; idx += 512) {
            int r = idx >> 3, i = idx & 7;
            cpasync16(adst + r * KSB + i * 16,
                      (const char*)(asrc + (nb2 + r) * HD) + co + i * 16);
        }
    };

    stageq(0);
    CP_COMMIT();    // group: B-all + A(0)

    const u32 aOff = (u32)((wr + (lane & 15)) * KSB + (lane >> 4) * 16);
    const u32 bOff = (u32)((wc + (lane & 15)) * KSB + (lane >> 4) * 16);
    const int cb = (lane & 3) * 2;

    float acc[2][NJ][4];
    #pragma unroll
    for (int m = 0; m < 2; m++)
        #pragma unroll
        for (int j = 0; j < NJ; j++) {
            acc[m][j][0] = 0.f; acc[m][j][1] = 0.f;
            acc[m][j][2] = 0.f; acc[m][j][3] = 0.f;
        }

    for (int q = 0; q < Q; q++) {
        if (q + 1 < Q) {
            stageq(q + 1);
            CP_COMMIT();
            asm volatile("cp.async.wait_group 1;" ::: "memory");
        } else {
            asm volatile("cp.async.wait_group 0;" ::: "memory");
        }
        __syncthreads();   // A(q) (and B on first iter) visible

        const u32 abuf = sb + (q & 1) * ABYT + aOff;
        const u32 bbuf = sb + SM_B + (q & 3) * BBYT + bOff;
        #pragma unroll
        for (int k16 = 0; k16 < 4; k16++) {
            u32 a0[4], a1[4];
            ldsm4(a0, abuf + k16 * 32);
            ldsm4(a1, abuf + 16 * KSB + k16 * 32);
            #pragma unroll
            for (int jp = 0; jp < NJ2; jp++) {
                u32 bb[4];
                ldsm4(bb, bbuf + jp * 16 * KSB + k16 * 32);
                mma16816(acc[0][2 * jp],     a0, bb[0], bb[2]);
                mma16816(acc[1][2 * jp],     a1, bb[0], bb[2]);
                mma16816(acc[0][2 * jp + 1], a0, bb[1], bb[3]);
                mma16816(acc[1][2 * jp + 1], a1, bb[1], bb[3]);
            }
        }

        if ((q & 3) == 3) {
            // ---- epilogue for this tile ----
            int nb = (bid + (q >> 2) * GRID) * 128;
            #pragma unroll
            for (int m = 0; m < 2; m++) {
                int n0 = nb + wr + m * 16 + (lane >> 2);
                #pragma unroll
                for (int j = 0; j < NJ; j++) {
                    int c = wc + j * 8 + cb;
                    float s0 = *(const float*)(smem + SM_SC + c * 4);
                    float s1 = *(const float*)(smem + SM_SC + (c + 1) * 4);
                    float h0 = *(const float*)(smem + SM_SH + c * 4);
                    float h1 = *(const float*)(smem + SM_SH + (c + 1) * 4);
                    #pragma unroll
                    for (int hh = 0; hh < 2; hh++) {
                        int n = n0 + hh * 8;
                        if (n >= NN) continue;
                        float vx = acc[m][j][hh * 2 + 0] * s0 + h0;
                        float vy = acc[m][j][hh * 2 + 1] * s1 + h1;
                        if (!LAST) {
                            vx = fmaxf(vx, 0.f);
                            vy = fmaxf(vy, 0.f);
                            __half2 hv = __floats2half2_rn(vx, vy);
                            *(u32*)((__half*)hout + (size_t)n * N_ + c) = *(u32*)&hv;
                        } else {
                            float2 o; o.x = vx; o.y = vy;
                            *(float2*)((float*)hout + (size_t)n * N_ + c) = o;
                        }
                    }
                }
            }
            // reset accumulators for next tile
            #pragma unroll
            for (int m = 0; m < 2; m++)
                #pragma unroll
                for (int j = 0; j < NJ; j++) {
                    acc[m][j][0] = 0.f; acc[m][j][1] = 0.f;
                    acc[m][j][2] = 0.f; acc[m][j][3] = 0.f;
                }
        }
        __syncthreads();   // all warps done reading A(q) before A(q+2) overwrites
    }
}

// ================= launch =================
extern "C" void kernel_launch(void* const* d_in, const int* in_sizes, int n_in,
                              void* d_out, int out_size) {
    const float* x    = (const float*)d_in[0];
    const int*   ei   = (const int*)  d_in[1];
    const float* Wl1  = (const float*)d_in[2];
    const float* bl1  = (const float*)d_in[3];
    const float* Wr1  = (const float*)d_in[4];
    const float* g1   = (const float*)d_in[5];
    const float* be1  = (const float*)d_in[6];
    const float* rm1  = (const float*)d_in[7];
    const float* rv1  = (const float*)d_in[8];
    const float* Wl2  = (const float*)d_in[9];
    const float* bl2  = (const float*)d_in[10];
    const float* Wr2  = (const float*)d_in[11];
    const float* g2   = (const float*)d_in[12];
    const float* be2  = (const float*)d_in[13];
    const float* rm2  = (const float*)d_in[14];
    const float* rv2  = (const float*)d_in[15];
    const float* Wl3  = (const float*)d_in[16];
    const float* bl3  = (const float*)d_in[17];
    const float* Wr3  = (const float*)d_in[18];
    const int* src = ei;
    const int* dst = ei + EE;
    float* out = (float*)d_out;

    __half *xh_p, *h_p, *b_p;
    cudaGetSymbolAddress((void**)&xh_p, g_xh);
    cudaGetSymbolAddress((void**)&h_p,  g_h);
    cudaGetSymbolAddress((void**)&b_p,  g_bimg);
    const __half* b1 = b_p;
    const __half* b2 = b_p + BIMG_L2;
    const __half* b3 = b_p + BIMG_L3;

    constexpr int SMEM12 = 2 * 128 * KSB + 4 * HD  * KSB + 1024;   // 111616
    constexpr int SMEM3  = 2 * 128 * KSB + 4 * OD3 * KSB + 1024;   // 74752
    cudaFuncSetAttribute(k_node<HD, false>, cudaFuncAttributeMaxDynamicSharedMemorySize, SMEM12);
    cudaFuncSetAttribute(k_node<OD3, true>, cudaFuncAttributeMaxDynamicSharedMemorySize, SMEM3);

    const int EB = (EE + 255) / 256;
    const int GB = (NN * 32 + 255) / 256;

    // CSR build + fp16 conversions + weight pack
    k_hist<<<EB, 256>>>(dst);
    k_scan<<<1, 1024>>>();
    k_slot<<<EB, 256>>>(src, dst);
    k_xhalf<<<(NN * HD / 8 + 255) / 256, 256>>>(x);
    k_bpackall<<<(3 * 4 * 64 * HD + 255) / 256, 256>>>(Wl1, Wr1, Wl2, Wr2, Wl3, Wr3);

    // layer 1
    k_gather<<<GB, 256>>>(xh_p);
    k_node<HD, false><<<GRID, 512, SMEM12>>>(xh_p, h_p, b1, bl1, g1, be1, rm1, rv1);

    // layer 2 (in place safe: node reads only its own rows of g_h / g_agg)
    k_gather<<<GB, 256>>>(h_p);
    k_node<HD, false><<<GRID, 512, SMEM12>>>(h_p, h_p, b2, bl2, g2, be2, rm2, rv2);

    // layer 3
    k_gather<<<GB, 256>>>(h_p);
    k_node<OD3, true><<<GRID, 512, SMEM3>>>(h_p, out, b3, bl3, bl3, bl3, bl3, bl3);
}